// round 15
// baseline (speedup 1.0000x reference)
#include <cuda_runtime.h>

#define NN 512
#define DD 32
#define TT 8192
#define TPB 128            // 4 CTAs x 128 threads, 1 neuron per thread
#define NCTA 4
#define TWO_PI 6.2831853071795864769f
#define INV_TWO_PI 0.15915494309189535f

// precomputed S[t] = sum_d x_t[d] * x_{t+1}[d]  (complex)
__device__ __align__(8) float2 Sbuf[TT];

// ---- packed f32x2 helpers ----
__device__ __forceinline__ unsigned long long ffma2(unsigned long long a,
                                                    unsigned long long b,
                                                    unsigned long long c) {
    unsigned long long d;
    asm("fma.rn.f32x2 %0, %1, %2, %3;" : "=l"(d) : "l"(a), "l"(b), "l"(c));
    return d;
}
__device__ __forceinline__ unsigned long long pack2(float lo, float hi) {
    unsigned long long r;
    asm("mov.b64 %0, {%1, %2};" : "=l"(r) : "f"(lo), "f"(hi));
    return r;
}
__device__ __forceinline__ void unpack2(unsigned long long v, float& lo, float& hi) {
    asm("mov.b64 {%0, %1}, %2;" : "=f"(lo), "=f"(hi) : "l"(v));
}
__device__ __forceinline__ float wrap2pi(float x) {
    return x - floorf(x * INV_TWO_PI) * TWO_PI;
}
__device__ __forceinline__ float frcp(float x) {
    float r;
    asm("rcp.approx.f32 %0, %1;" : "=f"(r) : "f"(x));
    return r;
}
__device__ __forceinline__ unsigned smem_u32(const void* p) {
    unsigned a;
    asm("{ .reg .u64 t; cvta.to.shared.u64 t, %1; cvt.u32.u64 %0, t; }"
        : "=r"(a) : "l"(p));
    return a;
}
__device__ __forceinline__ unsigned cluster_rank() {
    unsigned r;
    asm("mov.u32 %0, %%cluster_ctarank;" : "=r"(r));
    return r;
}
__device__ __forceinline__ void mb_init(unsigned a, unsigned cnt) {
    asm volatile("mbarrier.init.shared.b64 [%0], %1;" :: "r"(a), "r"(cnt) : "memory");
}
// store v into red slot of CTA c, then (after fence) arrive on CTA c's mbar
__device__ __forceinline__ void remote_st(unsigned addr, unsigned c, float v) {
    asm volatile("{\n\t"
        ".reg .b32 ra;\n\t"
        "mapa.shared::cluster.u32 ra, %0, %1;\n\t"
        "st.shared::cluster.b32 [ra], %2;\n\t"
        "}" :: "r"(addr), "r"(c), "r"(__float_as_uint(v)) : "memory");
}
__device__ __forceinline__ void remote_arrive(unsigned mbaddr, unsigned c) {
    asm volatile("{\n\t"
        ".reg .b32 rm;\n\t"
        "mapa.shared::cluster.u32 rm, %0, %1;\n\t"
        "mbarrier.arrive.shared::cluster.b64 _, [rm];\n\t"
        "}" :: "r"(mbaddr), "r"(c) : "memory");
}
__device__ __forceinline__ void mb_wait_par(unsigned a, unsigned par) {
    unsigned done;
    asm volatile("{\n\t"
        ".reg .pred p;\n\t"
        "mbarrier.try_wait.parity.acquire.cta.shared::cta.b64 p, [%1], %2;\n\t"
        "selp.b32 %0, 1, 0, p;\n\t"
        "}" : "=r"(done) : "r"(a), "r"(par) : "memory");
    if (!done) {
        asm volatile("{\n\t"
            ".reg .pred P1;\n\t"
            "W_%=:\n\t"
            "mbarrier.try_wait.parity.acquire.cta.shared::cta.b64 P1, [%0], %1, 0x989680;\n\t"
            "@P1 bra D_%=;\n\t"
            "bra W_%=;\n\t"
            "D_%=:\n\t"
            "}" :: "r"(a), "r"(par) : "memory");
    }
    asm volatile("fence.acq_rel.cluster;" ::: "memory");
}

// ---- parallel pre-kernel: S[t] for all t ----
__global__ void precomp_s(const float* __restrict__ Xr, const float* __restrict__ Xi) {
    int t = blockIdx.x * 256 + threadIdx.x;
    if (t >= TT) return;
    float sr = 0.f, si = 0.f;
    if (t + 1 < TT) {
        const float4* cr = (const float4*)(Xr + t * DD);
        const float4* ci = (const float4*)(Xi + t * DD);
        const float4* nr = (const float4*)(Xr + (t + 1) * DD);
        const float4* ni = (const float4*)(Xi + (t + 1) * DD);
#pragma unroll
        for (int j = 0; j < DD / 4; j++) {
            float4 a = cr[j], b = ci[j], c = nr[j], d = ni[j];
            sr += a.x * c.x - b.x * d.x;  si += a.x * d.x + b.x * c.x;
            sr += a.y * c.y - b.y * d.y;  si += a.y * d.y + b.y * c.y;
            sr += a.z * c.z - b.z * d.z;  si += a.z * d.z + b.z * c.z;
            sr += a.w * c.w - b.w * d.w;  si += a.w * d.w + b.w * c.w;
        }
    }
    Sbuf[t] = make_float2(sr, si);
}

__global__ __launch_bounds__(TPB, 1) __cluster_dims__(NCTA, 1, 1)
void rds_kernel(const float* __restrict__ Xr, const float* __restrict__ Xi,
                const float* __restrict__ tw, const float* __restrict__ Wr,
                const float* __restrict__ Wi, const float* __restrict__ phi0,
                const float* __restrict__ beta0, float* __restrict__ out) {
    const int tid  = threadIdx.x;
    const int lane = tid & 31;
    const int wid  = tid >> 5;              // 0..3
    const unsigned rank = cluster_rank();
    const int g = rank * TPB + tid;         // global neuron

    // 8-deep buffered x (warp skew <= 1 step; reader slots t-1,t+1, writer t+2)
    __shared__ __align__(16) float4 xsA[8][DD];     // (xr,xr,xi,xi) per d
    __shared__ __align__(16) float  xsB[8][2 * DD]; // interleaved (xr,xi)
    __shared__ float s_tgt[8];
    __shared__ __align__(16) float red[2][16];      // GLOBAL warp slots
    __shared__ __align__(8) unsigned long long mb[2];

    const unsigned mb0_a = smem_u32(&mb[0]);
    const unsigned mb1_a = smem_u32(&mb[1]);
    const unsigned red0_a = smem_u32(&red[0][0]);

    // factored W: W = alpha * A (fully unrolled indexing only! — R13 lesson)
    unsigned long long A[DD];               // 64 regs
    float alpha = 1.0f;
#pragma unroll
    for (int d = 0; d < DD; d++)
        A[d] = pack2(Wr[g * DD + d], Wi[g * DD + d]);
    float phi  = phi0[g];
    float beta = beta0[g];
    float lt   = 0.0f;
    float err  = 0.0f;                      // identical in every thread/CTA
    unsigned long long cprev = 0ull;        // pending A coefficient (c_{t-1})

    float* outs   = out;
    float* betas  = out + TT;
    float* gammas = out + TT + (size_t)TT * NN;

    // zero all x slots (slot 7 read at t=0 with cprev=0 — must be finite)
    for (int i = tid; i < 8 * DD; i += TPB) xsA[i / DD][i % DD] = make_float4(0, 0, 0, 0);
    for (int i = tid; i < 8 * 2 * DD; i += TPB) xsB[i / (2 * DD)][i % (2 * DD)] = 0.0f;
    __syncthreads();

    // prologue: x_0 -> slot0, x_1 -> slot1
    if (tid < DD) {
        float xr = Xr[tid], xi = Xi[tid];
        xsA[0][tid] = make_float4(xr, xr, xi, xi);
        xsB[0][2 * tid] = xr; xsB[0][2 * tid + 1] = xi;
        xr = Xr[DD + tid]; xi = Xi[DD + tid];
        xsA[1][tid] = make_float4(xr, xr, xi, xi);
        xsB[1][2 * tid] = xr; xsB[1][2 * tid + 1] = xi;
        if (tid == 0) { s_tgt[0] = tw[0]; s_tgt[1] = tw[1]; }
    }
    if (tid == 0) { mb_init(mb0_a, 16); mb_init(mb1_a, 16); }
    __syncthreads();
    asm volatile("barrier.cluster.arrive.aligned;" ::: "memory");
    asm volatile("barrier.cluster.wait.aligned;" ::: "memory");

    // Z_0 = A @ x_0 (alpha = 1)
    float zr, zi;
    {
        unsigned long long a0 = 0ull, a1 = 0ull, b0 = 0ull, b1 = 0ull;
        const ulonglong2* xa = (const ulonglong2*)xsA[0];
#pragma unroll
        for (int d = 0; d < DD; d += 2) {
            ulonglong2 v0 = xa[d], v1 = xa[d + 1];
            a0 = ffma2(A[d], v0.x, a0);     b0 = ffma2(A[d], v0.y, b0);
            a1 = ffma2(A[d + 1], v1.x, a1); b1 = ffma2(A[d + 1], v1.y, b1);
        }
        float a0l, a0h, a1l, a1h, b0l, b0h, b1l, b1h;
        unpack2(a0, a0l, a0h); unpack2(a1, a1l, a1h);
        unpack2(b0, b0l, b0h); unpack2(b1, b1l, b1h);
        zr = (a0l + a1l) - (b0h + b1h);
        zi = (b0l + b1l) + (a0h + a1h);
    }

    // pipelined head for step 0
    float dtl = __expf(-0.5f * beta) * 1e-3f;
    lt += dtl;
    float sn, cs;
    __sincosf(wrap2pi(10.0f * lt + phi), &sn, &cs);

#pragma unroll 1
    for (int t = 0; t < TT; t++) {
        const int rb = t & 1;
        const unsigned par = (unsigned)(t >> 1) & 1u;
        const unsigned mba = rb ? mb1_a : mb0_a;

        // ================= gate + warp partial + PUSH (early) =============
        float dot = cs * zr + sn * zi;
        float Y   = fmaxf(dot, 0.0f);
        float v   = Y * cs;
#pragma unroll
        for (int o = 16; o; o >>= 1)
            v += __shfl_xor_sync(0xffffffffu, v, o);
        if (lane == 0) {
            // write to GLOBAL slot rank*4+wid in every CTA -> identical red[]
            unsigned slot_a = red0_a + (unsigned)(rb * 16 + (int)rank * 4 + wid) * 4u;
#pragma unroll
            for (unsigned c = 0; c < NCTA; c++) remote_st(slot_a, c, v);
            asm volatile("fence.acq_rel.cluster;" ::: "memory");
#pragma unroll
            for (unsigned c = 0; c < NCTA; c++) remote_arrive(mba, c);
        }

        // prefetch x_{t+2}, tgt_{t+2}
        if (tid < DD && t + 2 < TT) {
            const int bp = (t + 2) & 7;
            float xr = Xr[(t + 2) * DD + tid];
            float xi = Xi[(t + 2) * DD + tid];
            xsA[bp][tid] = make_float4(xr, xr, xi, xi);
            xsB[bp][2 * tid]     = xr;
            xsB[bp][2 * tid + 1] = xi;
            if (tid == 0) s_tgt[bp] = tw[t + 2];
        }

        // ================= BULK (hides the DSMEM flight) ==================
        // lagged A materialization: A += c_{t-1} * x_{t-1}
        {
            const ulonglong2* xb = (const ulonglong2*)xsB[(t - 1) & 7];
#pragma unroll
            for (int j = 0; j < DD / 2; j++) {
                ulonglong2 u = xb[j];
                A[2 * j]     = ffma2(cprev, u.x, A[2 * j]);
                A[2 * j + 1] = ffma2(cprev, u.y, A[2 * j + 1]);
            }
        }
        // U = A_t @ x_{t+1}
        float ur, ui;
        {
            unsigned long long a0 = 0ull, a1 = 0ull, b0 = 0ull, b1 = 0ull;
            const ulonglong2* xa = (const ulonglong2*)xsA[(t + 1) & 7];
#pragma unroll
            for (int d = 0; d < DD; d += 2) {
                ulonglong2 v0 = xa[d], v1 = xa[d + 1];
                a0 = ffma2(A[d], v0.x, a0);     b0 = ffma2(A[d], v0.y, b0);
                a1 = ffma2(A[d + 1], v1.x, a1); b1 = ffma2(A[d + 1], v1.y, b1);
            }
            float a0l, a0h, a1l, a1h, b0l, b0h, b1l, b1h;
            unpack2(a0, a0l, a0h); unpack2(a1, a1l, a1h);
            unpack2(b0, b0l, b0h); unpack2(b1, b1l, b1h);
            ur = (a0l + a1l) - (b0h + b1h);
            ui = (b0l + b1l) + (a0h + a1h);
        }

        float2 S  = __ldg(&Sbuf[t]);
        float tgt = s_tgt[t & 7];
        // chain hoists
        float rcp_at = frcp(fabsf(tgt) + 0.01f);
        float dphi   = (2.0f / 512.0f) * (-tgt * sn) * dtl;
        float ex1    = 1.0f - __expf(-2.0f * dtl - 2e-9f);
        float gg     = 0.05f * Y * dtl;
        float y2dt   = Y * Y * dtl;

        // ================= WAIT + global sum + chain ======================
        mb_wait_par(mba, par);
        float4 r0 = *(const float4*)&red[rb][0];
        float4 r1 = *(const float4*)&red[rb][4];
        float4 r2 = *(const float4*)&red[rb][8];
        float4 r3 = *(const float4*)&red[rb][12];
        float out_v = (((r0.x + r0.y) + (r0.z + r0.w))
                    +  ((r1.x + r1.y) + (r1.z + r1.w)))
                    + (((r2.x + r2.y) + (r2.z + r2.w))
                    +  ((r3.x + r3.y) + (r3.z + r3.w)));

        err = 0.99f * err + 0.01f * fabsf(tgt - out_v);
        float btgt = 3.5f * __expf(-5.0f * (err * rcp_at));
        float a_s  = (btgt > beta) ? ex1 : 0.03278394f;   // 1-exp(-1/30)
        float bnew = beta + a_s * (btgt - beta);
        bnew = fminf(fmaxf(bnew, 0.005f), 5.0f);

        float ddc = bnew * y2dt;
        float one = 1.0f - ddc;
        float au  = alpha * one;                  // alpha_{t+1}
        zr = au * ur + gg * S.x;
        zi = au * ui + gg * S.y;

        if ((t & 127) == 127) {
            // renorm: fold alpha into A; pending coeff becomes gg
            unsigned long long apk = pack2(au, au);
#pragma unroll
            for (int d = 0; d < DD; d++)
                A[d] = ffma2(apk, A[d], 0ull);
            alpha = 1.0f;
            cprev = pack2(gg, gg);
        } else {
            float c = __fdividef(gg, au);
            alpha = au;
            cprev = pack2(c, c);
        }

        // outputs
        betas[t * NN + g]  = bnew;
        gammas[t * NN + g] = dtl * 1e3f;
        if (rank == 0 && tid == 0) outs[t] = out_v;

        // phase pull + wrap; pipelined head of next step
        float phin = phi + dphi;
        phin -= floorf(phin * INV_TWO_PI) * TWO_PI;
        phi  = phin;
        beta = bnew;
        dtl  = __expf(-0.5f * bnew) * 1e-3f;
        lt  += dtl;
        __sincosf(wrap2pi(10.0f * lt + phin), &sn, &cs);
    }

    // no CTA may exit while peer remote ops could still target its smem
    asm volatile("barrier.cluster.arrive.aligned;" ::: "memory");
    asm volatile("barrier.cluster.wait.aligned;" ::: "memory");
}

extern "C" void kernel_launch(void* const* d_in, const int* in_sizes, int n_in,
                              void* d_out, int out_size) {
    const float* Xr    = (const float*)d_in[0];
    const float* Xi    = (const float*)d_in[1];
    const float* tw    = (const float*)d_in[2];
    const float* Wr    = (const float*)d_in[3];
    const float* Wi    = (const float*)d_in[4];
    const float* phi0  = (const float*)d_in[5];
    const float* beta0 = (const float*)d_in[6];
    float* out = (float*)d_out;
    precomp_s<<<TT / 256, 256>>>(Xr, Xi);
    rds_kernel<<<NCTA, TPB>>>(Xr, Xi, tw, Wr, Wi, phi0, beta0, out);
}

// round 16
// speedup vs baseline: 1.0019x; 1.0019x over previous
#include <cuda_runtime.h>

#define NN 512
#define DD 32
#define TT 8192
#define TPB 256            // 2 CTAs x 256 threads, 1 neuron per thread
#define NCTA 2
#define TWO_PI 6.2831853071795864769f
#define INV_TWO_PI 0.15915494309189535f

// precomputed S[t] = sum_d x_t[d] * x_{t+1}[d]  (complex)
__device__ __align__(8) float2 Sbuf[TT];

// ---- packed f32x2 helpers ----
__device__ __forceinline__ unsigned long long ffma2(unsigned long long a,
                                                    unsigned long long b,
                                                    unsigned long long c) {
    unsigned long long d;
    asm("fma.rn.f32x2 %0, %1, %2, %3;" : "=l"(d) : "l"(a), "l"(b), "l"(c));
    return d;
}
__device__ __forceinline__ unsigned long long pack2(float lo, float hi) {
    unsigned long long r;
    asm("mov.b64 %0, {%1, %2};" : "=l"(r) : "f"(lo), "f"(hi));
    return r;
}
__device__ __forceinline__ void unpack2(unsigned long long v, float& lo, float& hi) {
    asm("mov.b64 {%0, %1}, %2;" : "=f"(lo), "=f"(hi) : "l"(v));
}
__device__ __forceinline__ float wrap2pi(float x) {
    return x - floorf(x * INV_TWO_PI) * TWO_PI;
}
__device__ __forceinline__ float frcp(float x) {
    float r;
    asm("rcp.approx.f32 %0, %1;" : "=f"(r) : "f"(x));
    return r;
}
__device__ __forceinline__ unsigned smem_u32(const void* p) {
    unsigned a;
    asm("{ .reg .u64 t; cvta.to.shared.u64 t, %1; cvt.u32.u64 %0, t; }"
        : "=r"(a) : "l"(p));
    return a;
}
__device__ __forceinline__ unsigned cluster_rank() {
    unsigned r;
    asm("mov.u32 %0, %%cluster_ctarank;" : "=r"(r));
    return r;
}
__device__ __forceinline__ void mb_init(unsigned a, unsigned cnt) {
    asm volatile("mbarrier.init.shared.b64 [%0], %1;" :: "r"(a), "r"(cnt) : "memory");
}
// plain data store into CTA c's red slot
__device__ __forceinline__ void remote_st(unsigned addr, unsigned c, float v) {
    asm volatile("{\n\t"
        ".reg .b32 ra;\n\t"
        "mapa.shared::cluster.u32 ra, %0, %1;\n\t"
        "st.shared::cluster.b32 [ra], %2;\n\t"
        "}" :: "r"(addr), "r"(c), "r"(__float_as_uint(v)) : "memory");
}
// release-arrive at cluster scope: orders the prior data store, no fence needed
__device__ __forceinline__ void remote_arrive_rel(unsigned mbaddr, unsigned c) {
    asm volatile("{\n\t"
        ".reg .b32 rm;\n\t"
        "mapa.shared::cluster.u32 rm, %0, %1;\n\t"
        "mbarrier.arrive.release.cluster.shared::cluster.b64 _, [rm];\n\t"
        "}" :: "r"(mbaddr), "r"(c) : "memory");
}
// acquire at CLUSTER scope (pairs with the release-arrive; no trailing fence)
__device__ __forceinline__ void mb_wait_par(unsigned a, unsigned par) {
    unsigned done;
    asm volatile("{\n\t"
        ".reg .pred p;\n\t"
        "mbarrier.try_wait.parity.acquire.cluster.shared::cta.b64 p, [%1], %2;\n\t"
        "selp.b32 %0, 1, 0, p;\n\t"
        "}" : "=r"(done) : "r"(a), "r"(par) : "memory");
    if (!done) {
        asm volatile("{\n\t"
            ".reg .pred P1;\n\t"
            "W_%=:\n\t"
            "mbarrier.try_wait.parity.acquire.cluster.shared::cta.b64 P1, [%0], %1, 0x989680;\n\t"
            "@P1 bra D_%=;\n\t"
            "bra W_%=;\n\t"
            "D_%=:\n\t"
            "}" :: "r"(a), "r"(par) : "memory");
    }
}

// ---- parallel pre-kernel: S[t] for all t ----
__global__ void precomp_s(const float* __restrict__ Xr, const float* __restrict__ Xi) {
    int t = blockIdx.x * 256 + threadIdx.x;
    if (t >= TT) return;
    float sr = 0.f, si = 0.f;
    if (t + 1 < TT) {
        const float4* cr = (const float4*)(Xr + t * DD);
        const float4* ci = (const float4*)(Xi + t * DD);
        const float4* nr = (const float4*)(Xr + (t + 1) * DD);
        const float4* ni = (const float4*)(Xi + (t + 1) * DD);
#pragma unroll
        for (int j = 0; j < DD / 4; j++) {
            float4 a = cr[j], b = ci[j], c = nr[j], d = ni[j];
            sr += a.x * c.x - b.x * d.x;  si += a.x * d.x + b.x * c.x;
            sr += a.y * c.y - b.y * d.y;  si += a.y * d.y + b.y * c.y;
            sr += a.z * c.z - b.z * d.z;  si += a.z * d.z + b.z * c.z;
            sr += a.w * c.w - b.w * d.w;  si += a.w * d.w + b.w * c.w;
        }
    }
    Sbuf[t] = make_float2(sr, si);
}

__global__ __launch_bounds__(TPB, 1) __cluster_dims__(NCTA, 1, 1)
void rds_kernel(const float* __restrict__ Xr, const float* __restrict__ Xi,
                const float* __restrict__ tw, const float* __restrict__ Wr,
                const float* __restrict__ Wi, const float* __restrict__ phi0,
                const float* __restrict__ beta0, float* __restrict__ out) {
    const int tid  = threadIdx.x;
    const int lane = tid & 31;
    const int wid  = tid >> 5;              // 0..7
    const unsigned rank = cluster_rank();
    const int g = rank * TPB + tid;         // global neuron

    // 8-deep buffered x (warp skew <= 1 step around the mbar)
    __shared__ __align__(16) float4 xsA[8][DD];     // (xr,xr,xi,xi) per d
    __shared__ __align__(16) float  xsB[8][2 * DD]; // interleaved (xr,xi)
    __shared__ float s_tgt[8];
    __shared__ __align__(16) float red[2][16];      // GLOBAL warp slots
    __shared__ __align__(8) unsigned long long mb[2];

    const unsigned mb0_a = smem_u32(&mb[0]);
    const unsigned mb1_a = smem_u32(&mb[1]);
    const unsigned red0_a = smem_u32(&red[0][0]);

    // factored W: W = alpha * A (fully unrolled indexing only! — R13 lesson)
    unsigned long long A[DD];               // 64 regs
    float alpha = 1.0f;
#pragma unroll
    for (int d = 0; d < DD; d++)
        A[d] = pack2(Wr[g * DD + d], Wi[g * DD + d]);
    float phi  = phi0[g];
    float beta = beta0[g];
    float lt   = 0.0f;
    float err  = 0.0f;                      // identical in every thread/CTA
    unsigned long long cprev = 0ull;        // pending A coefficient (c_{t-1})

    float* outs   = out;
    float* betas  = out + TT;
    float* gammas = out + TT + (size_t)TT * NN;

    // zero all x slots (slot 7 read at t=0 with cprev=0 — must be finite)
    for (int i = tid; i < 8 * DD; i += TPB) xsA[i / DD][i % DD] = make_float4(0, 0, 0, 0);
    for (int i = tid; i < 8 * 2 * DD; i += TPB) xsB[i / (2 * DD)][i % (2 * DD)] = 0.0f;
    __syncthreads();

    // prologue: x_0 -> slot0, x_1 -> slot1
    if (tid < DD) {
        float xr = Xr[tid], xi = Xi[tid];
        xsA[0][tid] = make_float4(xr, xr, xi, xi);
        xsB[0][2 * tid] = xr; xsB[0][2 * tid + 1] = xi;
        xr = Xr[DD + tid]; xi = Xi[DD + tid];
        xsA[1][tid] = make_float4(xr, xr, xi, xi);
        xsB[1][2 * tid] = xr; xsB[1][2 * tid + 1] = xi;
        if (tid == 0) { s_tgt[0] = tw[0]; s_tgt[1] = tw[1]; }
    }
    if (tid == 0) { mb_init(mb0_a, 16); mb_init(mb1_a, 16); }
    __syncthreads();
    asm volatile("barrier.cluster.arrive.aligned;" ::: "memory");
    asm volatile("barrier.cluster.wait.aligned;" ::: "memory");

    // Z_0 = A @ x_0 (alpha = 1)
    float zr, zi;
    {
        unsigned long long a0 = 0ull, a1 = 0ull, b0 = 0ull, b1 = 0ull;
        const ulonglong2* xa = (const ulonglong2*)xsA[0];
#pragma unroll
        for (int d = 0; d < DD; d += 2) {
            ulonglong2 v0 = xa[d], v1 = xa[d + 1];
            a0 = ffma2(A[d], v0.x, a0);     b0 = ffma2(A[d], v0.y, b0);
            a1 = ffma2(A[d + 1], v1.x, a1); b1 = ffma2(A[d + 1], v1.y, b1);
        }
        float a0l, a0h, a1l, a1h, b0l, b0h, b1l, b1h;
        unpack2(a0, a0l, a0h); unpack2(a1, a1l, a1h);
        unpack2(b0, b0l, b0h); unpack2(b1, b1l, b1h);
        zr = (a0l + a1l) - (b0h + b1h);
        zi = (b0l + b1l) + (a0h + a1h);
    }

    // pipelined head for step 0
    float dtl = __expf(-0.5f * beta) * 1e-3f;
    lt += dtl;
    float sn, cs;
    __sincosf(wrap2pi(10.0f * lt + phi), &sn, &cs);

#pragma unroll 1
    for (int t = 0; t < TT; t++) {
        const int rb = t & 1;
        const unsigned par = (unsigned)(t >> 1) & 1u;
        const unsigned mba = rb ? mb1_a : mb0_a;

        // ================= gate + warp partial + PUSH (early) =============
        float dot = cs * zr + sn * zi;
        float Y   = fmaxf(dot, 0.0f);
        float v   = Y * cs;
#pragma unroll
        for (int o = 16; o; o >>= 1)
            v += __shfl_xor_sync(0xffffffffu, v, o);
        if (lane == 0) {
            // write to GLOBAL slot rank*8+wid in both CTAs -> identical red[]
            unsigned slot_a = red0_a + (unsigned)(rb * 16 + (int)rank * 8 + wid) * 4u;
#pragma unroll
            for (unsigned c = 0; c < NCTA; c++) remote_st(slot_a, c, v);
#pragma unroll
            for (unsigned c = 0; c < NCTA; c++) remote_arrive_rel(mba, c);
        }

        // prefetch x_{t+2}, tgt_{t+2}
        if (tid < DD && t + 2 < TT) {
            const int bp = (t + 2) & 7;
            float xr = Xr[(t + 2) * DD + tid];
            float xi = Xi[(t + 2) * DD + tid];
            xsA[bp][tid] = make_float4(xr, xr, xi, xi);
            xsB[bp][2 * tid]     = xr;
            xsB[bp][2 * tid + 1] = xi;
            if (tid == 0) s_tgt[bp] = tw[t + 2];
        }

        // ================= BULK (hides the DSMEM flight) ==================
        // lagged A materialization: A += c_{t-1} * x_{t-1}
        {
            const ulonglong2* xb = (const ulonglong2*)xsB[(t - 1) & 7];
#pragma unroll
            for (int j = 0; j < DD / 2; j++) {
                ulonglong2 u = xb[j];
                A[2 * j]     = ffma2(cprev, u.x, A[2 * j]);
                A[2 * j + 1] = ffma2(cprev, u.y, A[2 * j + 1]);
            }
        }
        // U = A_t @ x_{t+1}
        float ur, ui;
        {
            unsigned long long a0 = 0ull, a1 = 0ull, b0 = 0ull, b1 = 0ull;
            const ulonglong2* xa = (const ulonglong2*)xsA[(t + 1) & 7];
#pragma unroll
            for (int d = 0; d < DD; d += 2) {
                ulonglong2 v0 = xa[d], v1 = xa[d + 1];
                a0 = ffma2(A[d], v0.x, a0);     b0 = ffma2(A[d], v0.y, b0);
                a1 = ffma2(A[d + 1], v1.x, a1); b1 = ffma2(A[d + 1], v1.y, b1);
            }
            float a0l, a0h, a1l, a1h, b0l, b0h, b1l, b1h;
            unpack2(a0, a0l, a0h); unpack2(a1, a1l, a1h);
            unpack2(b0, b0l, b0h); unpack2(b1, b1l, b1h);
            ur = (a0l + a1l) - (b0h + b1h);
            ui = (b0l + b1l) + (a0h + a1h);
        }

        float2 S  = __ldg(&Sbuf[t]);
        float tgt = s_tgt[t & 7];
        // chain hoists
        float rcp_at = frcp(fabsf(tgt) + 0.01f);
        float dphi   = (2.0f / 512.0f) * (-tgt * sn) * dtl;
        float ex1    = 1.0f - __expf(-2.0f * dtl - 2e-9f);
        float gg     = 0.05f * Y * dtl;
        float y2dt   = Y * Y * dtl;

        // ================= WAIT + global sum + chain ======================
        mb_wait_par(mba, par);
        float4 r0 = *(const float4*)&red[rb][0];
        float4 r1 = *(const float4*)&red[rb][4];
        float4 r2 = *(const float4*)&red[rb][8];
        float4 r3 = *(const float4*)&red[rb][12];
        float out_v = (((r0.x + r0.y) + (r0.z + r0.w))
                    +  ((r1.x + r1.y) + (r1.z + r1.w)))
                    + (((r2.x + r2.y) + (r2.z + r2.w))
                    +  ((r3.x + r3.y) + (r3.z + r3.w)));

        err = 0.99f * err + 0.01f * fabsf(tgt - out_v);
        float btgt = 3.5f * __expf(-5.0f * (err * rcp_at));
        float a_s  = (btgt > beta) ? ex1 : 0.03278394f;   // 1-exp(-1/30)
        float bnew = beta + a_s * (btgt - beta);
        bnew = fminf(fmaxf(bnew, 0.005f), 5.0f);

        float ddc = bnew * y2dt;
        float one = 1.0f - ddc;
        float au  = alpha * one;                  // alpha_{t+1}
        zr = au * ur + gg * S.x;
        zi = au * ui + gg * S.y;

        if ((t & 127) == 127) {
            // renorm: fold alpha into A; pending coeff becomes gg
            unsigned long long apk = pack2(au, au);
#pragma unroll
            for (int d = 0; d < DD; d++)
                A[d] = ffma2(apk, A[d], 0ull);
            alpha = 1.0f;
            cprev = pack2(gg, gg);
        } else {
            float c = __fdividef(gg, au);
            alpha = au;
            cprev = pack2(c, c);
        }

        // outputs
        betas[t * NN + g]  = bnew;
        gammas[t * NN + g] = dtl * 1e3f;
        if (rank == 0 && tid == 0) outs[t] = out_v;

        // phase pull + wrap; pipelined head of next step
        float phin = phi + dphi;
        phin -= floorf(phin * INV_TWO_PI) * TWO_PI;
        phi  = phin;
        beta = bnew;
        dtl  = __expf(-0.5f * bnew) * 1e-3f;
        lt  += dtl;
        __sincosf(wrap2pi(10.0f * lt + phin), &sn, &cs);
    }

    // no CTA may exit while peer remote ops could still target its smem
    asm volatile("barrier.cluster.arrive.aligned;" ::: "memory");
    asm volatile("barrier.cluster.wait.aligned;" ::: "memory");
}

extern "C" void kernel_launch(void* const* d_in, const int* in_sizes, int n_in,
                              void* d_out, int out_size) {
    const float* Xr    = (const float*)d_in[0];
    const float* Xi    = (const float*)d_in[1];
    const float* tw    = (const float*)d_in[2];
    const float* Wr    = (const float*)d_in[3];
    const float* Wi    = (const float*)d_in[4];
    const float* phi0  = (const float*)d_in[5];
    const float* beta0 = (const float*)d_in[6];
    float* out = (float*)d_out;
    precomp_s<<<TT / 256, 256>>>(Xr, Xi);
    rds_kernel<<<NCTA, TPB>>>(Xr, Xi, tw, Wr, Wi, phi0, beta0, out);
}